// round 11
// baseline (speedup 1.0000x reference)
#include <cuda_runtime.h>
#include <cuda_bf16.h>
#include <cstdint>
#include <math.h>

#define N_DATA 100000
#define NP     100352              // 1568 * 64
#define TILE   64
#define N_TILES (NP / TILE)        // 1568
#define NSPLIT 8
#define TPS    (N_TILES / NSPLIT)  // 196 tiles per split
#define SPLIT_PTS (TPS * TILE)     // 12544
#define D      64
#define BQ     2048
#define QBK    64                  // queries per screening CTA (M)
#define KNN    20
#define NCAND  24                  // survivors per (query, split)
#define TCAND  (NSPLIT * NCAND)    // 192

__device__ float g_bt[NP * D];     // tf32-rounded, k-permuted, point-major rows
__device__ float g_pp[NP];         // exact fp32 ||p||^2 (1e30 pad)
__device__ int   g_candI[BQ * TCAND];

// smem byte offsets for scr_k (Q/B/Dist rows: 68-float pitch)
#define OFF_Q    0                 // 64 x 68 floats = 17408
#define OFF_B    17408             // [buf] 17408 : ends 52224
#define OFF_DIST 52224             // 64 x 68 floats
#define OFF_PP   69632             // 2 x 64 floats
#define OFF_QQ   70144             // 64 floats
#define SCR_SMEM 70400
// epilogue lists alias Q/B region
#define OFF_LD   0                 // 256*NCAND floats = 24576
#define OFF_LI   24576

// ---------------------------------------------------------------------------
__device__ __forceinline__ void cp_async16(unsigned s, const void* gmem) {
    asm volatile("cp.async.cg.shared.global [%0], [%1], 16;" :: "r"(s), "l"(gmem));
}
#define CP_COMMIT() asm volatile("cp.async.commit_group;")
#define CP_WAIT1()  asm volatile("cp.async.wait_group 1;")
#define CP_WAIT0()  asm volatile("cp.async.wait_group 0;")

__device__ __forceinline__ unsigned smem_u32(const void* p) {
    unsigned a;
    asm("{ .reg .u64 t; cvta.to.shared.u64 t, %1; cvt.u32.u64 %0, t; }"
        : "=r"(a) : "l"(p));
    return a;
}
__device__ __forceinline__ unsigned f2u(float x) { return __float_as_uint(x); }

__device__ __forceinline__ void mma_tf32(float* c,
    unsigned a0, unsigned a1, unsigned a2, unsigned a3,
    unsigned b0, unsigned b1)
{
    asm volatile(
        "mma.sync.aligned.m16n8k8.row.col.f32.tf32.tf32.f32 "
        "{%0,%1,%2,%3}, {%4,%5,%6,%7}, {%8,%9}, {%0,%1,%2,%3};"
        : "+f"(c[0]), "+f"(c[1]), "+f"(c[2]), "+f"(c[3])
        : "r"(a0), "r"(a1), "r"(a2), "r"(a3), "r"(b0), "r"(b1));
}

__device__ __forceinline__ void insC(float d, int idx, float* best, int* bestI,
                                     float& kth) {
    if (d < kth) {
#pragma unroll
        for (int k = 0; k < NCAND; k++) {
            if (d < best[k]) {
                float td = best[k]; best[k] = d; d = td;
                int ti = bestI[k]; bestI[k] = idx; idx = ti;
            }
        }
        kth = best[NCAND - 1];
    }
}

// k-permutation within each 8-chunk so mma fragment pairs (k, k+4) are
// adjacent floats (single LDS.64 per fragment): phys = (k&3)*2 + ((k>>2)&1)
__device__ __forceinline__ int kperm(int k) {
    return (k >> 3) * 8 + (k & 3) * 2 + ((k >> 2) & 1);
}

// ---------------------------------------------------------------------------
// Prep: tf32-round data into k-permuted point-major rows + exact ||p||^2
// ---------------------------------------------------------------------------
__global__ void prep_k(const float* __restrict__ data) {
    int p = blockIdx.x * 256 + threadIdx.x;
    if (p >= NP) return;
    bool v = p < N_DATA;
    float pp = 0.f;
#pragma unroll
    for (int c8 = 0; c8 < 8; c8++) {
        float buf[8];
#pragma unroll
        for (int k = 0; k < 8; k++) {
            float x = v ? data[p * D + c8 * 8 + k] : 0.f;
            pp += x * x;
            unsigned h; asm volatile("cvt.rna.tf32.f32 %0, %1;" : "=r"(h) : "f"(x));
            buf[(k & 3) * 2 + ((k >> 2) & 1)] = __uint_as_float(h);
        }
        *reinterpret_cast<float4*>(&g_bt[p * D + c8 * 8]) =
            make_float4(buf[0], buf[1], buf[2], buf[3]);
        *reinterpret_cast<float4*>(&g_bt[p * D + c8 * 8 + 4]) =
            make_float4(buf[4], buf[5], buf[6], buf[7]);
    }
    g_pp[p] = v ? pp : 1e30f;
}

// ---------------------------------------------------------------------------
// MLP: x_dot = relu([x,t] @ W1 + b1) @ W2 + b2 ; write into out[:, 0:64]
// ---------------------------------------------------------------------------
__global__ __launch_bounds__(256) void mlp_k(
    const float* __restrict__ t, const float* __restrict__ z,
    const float* __restrict__ W1, const float* __restrict__ b1,
    const float* __restrict__ W2, const float* __restrict__ b2,
    float* __restrict__ out)
{
    __shared__ float sIn[16 * 68];
    __shared__ float sH[16 * 258];
    int tid = threadIdx.x;
    int r0 = blockIdx.x * 16;
    float tv = t[0];
    for (int i = tid; i < 16 * 65; i += 256) {
        int r = i / 65, c = i % 65;
        sIn[r * 68 + c] = (c < 64) ? z[(r0 + r) * 66 + c] : tv;
    }
    __syncthreads();
    {
        int r = tid & 15, jb = tid >> 4;
#pragma unroll
        for (int jj = 0; jj < 16; jj++) {
            int j = jb + jj * 16;
            float acc = b1[j];
#pragma unroll
            for (int i = 0; i < 65; i++) acc += sIn[r * 68 + i] * W1[i * 256 + j];
            sH[r * 258 + j] = fmaxf(acc, 0.f);
        }
    }
    __syncthreads();
    {
        int r = tid >> 4, db = tid & 15;
        int d0 = db * 4;
        float a0 = b2[d0], a1 = b2[d0 + 1], a2 = b2[d0 + 2], a3 = b2[d0 + 3];
#pragma unroll 8
        for (int j = 0; j < 256; j++) {
            float hv = sH[r * 258 + j];
            float4 w = *reinterpret_cast<const float4*>(W2 + j * 64 + d0);
            a0 += hv * w.x; a1 += hv * w.y; a2 += hv * w.z; a3 += hv * w.w;
        }
        int gq = r0 + r;
        out[gq * 66 + d0 + 0] = a0;
        out[gq * 66 + d0 + 1] = a1;
        out[gq * 66 + d0 + 2] = a2;
        out[gq * 66 + d0 + 3] = a3;
    }
}

// ---------------------------------------------------------------------------
// Screening: single tf32 mma product, 64q x 64p tiles, fused top-24.
// 8 warps: warp = (mstripe = wid>>1 [m16], nhalf = wid&1 [n32]).
// ---------------------------------------------------------------------------
__device__ __forceinline__ void loadB(unsigned smb, int tile, int buf, int tid) {
    const char* src = (const char*)g_bt + (size_t)tile * 16384;
    unsigned dst = smb + OFF_B + buf * 17408;
#pragma unroll
    for (int i = 0; i < 4; i++) {
        int c = tid + i * 256;             // 1024 = 64 rows x 16 chunks
        int r = c >> 4, ch = c & 15;
        cp_async16(dst + r * 272 + ch * 16, src + r * 256 + ch * 16);
    }
    if (tid < 16)
        cp_async16(smb + OFF_PP + buf * 256 + tid * 16,
                   (const char*)g_pp + (size_t)tile * 256 + tid * 16);
}

__global__ __launch_bounds__(256, 2) void scr_k(const float* __restrict__ z)
{
    extern __shared__ char sm[];
    unsigned smb = smem_u32(sm);
    int tid = threadIdx.x, lane = tid & 31, wid = tid >> 5;
    int q0 = blockIdx.x * QBK;
    int split = blockIdx.y;
    int tb = split * TPS;

    loadB(smb, tb + 0, 0, tid); CP_COMMIT();
    loadB(smb, tb + 1, 1, tid); CP_COMMIT();

    // stage queries: tf32-rounded, k-permuted, 68-float pitch
    float* Qt = reinterpret_cast<float*>(sm + OFF_Q);
#pragma unroll
    for (int i = 0; i < 2; i++) {
        int task = tid + i * 256;          // 512 = 64 rows x 8 chunks
        int r = task >> 3, c8 = task & 7;
#pragma unroll
        for (int k = 0; k < 8; k++) {
            float x = z[(q0 + r) * 66 + c8 * 8 + k];
            unsigned h; asm volatile("cvt.rna.tf32.f32 %0, %1;" : "=r"(h) : "f"(x));
            Qt[r * 68 + c8 * 8 + (k & 3) * 2 + ((k >> 2) & 1)] = __uint_as_float(h);
        }
    }
    if (tid < QBK) {
        float s = 0.f;
#pragma unroll 8
        for (int k = 0; k < D; k++) { float x = z[(q0 + tid) * 66 + k]; s += x * x; }
        *reinterpret_cast<float*>(sm + OFF_QQ + tid * 4) = s;
    }
    __syncthreads();

    int mstripe = wid >> 1, nhalf = wid & 1;
    int g = lane >> 2, tm = lane & 3;
    int r0q = mstripe * 16 + g, r1q = r0q + 8;
    float qq0 = *reinterpret_cast<float*>(sm + OFF_QQ + r0q * 4);
    float qq1 = *reinterpret_cast<float*>(sm + OFF_QQ + r1q * 4);

    float best[NCAND]; int bestI[NCAND]; float kth = 3.4e38f;
#pragma unroll
    for (int k = 0; k < NCAND; k++) { best[k] = 3.4e38f; bestI[k] = 0; }

    int sq_q = tid >> 2, sgrp = tid & 3;   // scan: 1 query x 16 points

    for (int t = 0; t < TPS; t++) {
        int cur = t & 1;
        if (t + 1 < TPS) CP_WAIT1(); else CP_WAIT0();
        __syncthreads();                   // B(t) ready; Dist(t-1) consumed

        float acc[4][4];
#pragma unroll
        for (int nt = 0; nt < 4; nt++)
#pragma unroll
            for (int i = 0; i < 4; i++) acc[nt][i] = 0.f;

        const float* Bt = reinterpret_cast<const float*>(sm + OFF_B + cur * 17408);
#pragma unroll
        for (int kc = 0; kc < 8; kc++) {
            int ko = kc * 8 + 2 * tm;
            float2 a0 = *reinterpret_cast<const float2*>(&Qt[r0q * 68 + ko]);
            float2 a1 = *reinterpret_cast<const float2*>(&Qt[r1q * 68 + ko]);
#pragma unroll
            for (int nt = 0; nt < 4; nt++) {
                int pr = nhalf * 32 + nt * 8 + g;
                float2 b = *reinterpret_cast<const float2*>(&Bt[pr * 68 + ko]);
                mma_tf32(acc[nt], f2u(a0.x), f2u(a1.x), f2u(a0.y), f2u(a1.y),
                         f2u(b.x), f2u(b.y));
            }
        }

        // sq = qq + pp - 2*dot -> Dist
        const float* pp = reinterpret_cast<const float*>(sm + OFF_PP + cur * 256);
        float* Dist = reinterpret_cast<float*>(sm + OFF_DIST);
#pragma unroll
        for (int nt = 0; nt < 4; nt++) {
            int c0 = nhalf * 32 + nt * 8 + 2 * tm;
            float pp0 = pp[c0], pp1 = pp[c0 + 1];
            *reinterpret_cast<float2*>(&Dist[r0q * 68 + c0]) =
                make_float2(qq0 + pp0 - 2.f * acc[nt][0],
                            qq0 + pp1 - 2.f * acc[nt][1]);
            *reinterpret_cast<float2*>(&Dist[r1q * 68 + c0]) =
                make_float2(qq1 + pp0 - 2.f * acc[nt][2],
                            qq1 + pp1 - 2.f * acc[nt][3]);
        }
        __syncthreads();                   // Dist complete; B(cur) consumed

        if (t + 2 < TPS) { loadB(smb, tb + t + 2, cur, tid); CP_COMMIT(); }

        // scan Dist, guarded insert
        const float* Dist2 = reinterpret_cast<const float*>(sm + OFF_DIST);
        int pb = split * SPLIT_PTS + t * TILE + sgrp * 16;
#pragma unroll
        for (int c4 = 0; c4 < 4; c4++) {
            float4 v = *reinterpret_cast<const float4*>(
                &Dist2[sq_q * 68 + sgrp * 16 + c4 * 4]);
            insC(v.x, pb + c4 * 4 + 0, best, bestI, kth);
            insC(v.y, pb + c4 * 4 + 1, best, bestI, kth);
            insC(v.z, pb + c4 * 4 + 2, best, bestI, kth);
            insC(v.w, pb + c4 * 4 + 3, best, bestI, kth);
        }
    }
    __syncthreads();

    // dump lists (alias Q/B smem), merge 4 per query -> per-split top-24
    float* listD = reinterpret_cast<float*>(sm + OFF_LD);
    int*   listI = reinterpret_cast<int*>(sm + OFF_LI);
#pragma unroll
    for (int k = 0; k < NCAND; k++) {
        listD[tid * NCAND + k] = best[k];
        listI[tid * NCAND + k] = bestI[k];
    }
    __syncthreads();
    if (tid < QBK) {
        int ptr[4] = {0, 0, 0, 0};
        int gbase = (q0 + tid) * TCAND + split * NCAND;
        for (int o = 0; o < NCAND; o++) {
            float bd = 3.5e38f; int bl = 0;
#pragma unroll
            for (int l = 0; l < 4; l++) {
                if (ptr[l] < NCAND) {
                    float v = listD[(tid * 4 + l) * NCAND + ptr[l]];
                    if (v < bd) { bd = v; bl = l; }
                }
            }
            g_candI[gbase + o] = listI[(tid * 4 + bl) * NCAND + ptr[bl]];
            ptr[bl]++;
        }
    }
}

// ---------------------------------------------------------------------------
// Final: exact fp32 refine of TCAND candidates/query, top-20, weights, metrics.
// One warp per query, 8 queries per CTA.
// ---------------------------------------------------------------------------
__global__ __launch_bounds__(256) void fin2_k(
    const float* __restrict__ z, const float* __restrict__ data,
    const float* __restrict__ velocity, float* __restrict__ out)
{
    __shared__ float sQ[8][64];
    __shared__ float sqq[8];
    __shared__ float sCD[8][TCAND];
    __shared__ int   sCI[8][TCAND];
    __shared__ float selW[8][KNN];
    __shared__ int   selI[8][KNN];
    int tid = threadIdx.x, w = tid >> 5, l = tid & 31;
    int qi = blockIdx.x * 8 + w;

    float part = 0.f;
    for (int k = l; k < 64; k += 32) {
        float x = z[qi * 66 + k];
        sQ[w][k] = x; part += x * x;
    }
#pragma unroll
    for (int o = 16; o; o >>= 1) part += __shfl_xor_sync(0xffffffffu, part, o);
    if (l == 0) sqq[w] = part;
    __syncwarp();
    float qq = sqq[w];

#pragma unroll
    for (int j = 0; j < TCAND / 32; j++) {
        int c = l * (TCAND / 32) + j;
        int idx = g_candI[qi * TCAND + c];
        float dt = 0.f, pp = 0.f;
#pragma unroll
        for (int k4 = 0; k4 < 16; k4++) {
            float4 p = *reinterpret_cast<const float4*>(&data[idx * 64 + k4 * 4]);
            pp += p.x * p.x + p.y * p.y + p.z * p.z + p.w * p.w;
            dt += sQ[w][k4 * 4 + 0] * p.x + sQ[w][k4 * 4 + 1] * p.y
                + sQ[w][k4 * 4 + 2] * p.z + sQ[w][k4 * 4 + 3] * p.w;
        }
        sCD[w][c] = qq + pp - 2.f * dt;
        sCI[w][c] = idx;
    }
    __syncwarp();

    if (l == 0) {
        float best[KNN]; int bi[KNN]; float kth = 3.4e38f;
#pragma unroll
        for (int k = 0; k < KNN; k++) { best[k] = 3.4e38f; bi[k] = 0; }
        for (int c = 0; c < TCAND; c++) {
            float d = sCD[w][c]; int idx = sCI[w][c];
            if (d < kth) {
#pragma unroll
                for (int k = 0; k < KNN; k++) {
                    if (d < best[k]) {
                        float td = best[k]; best[k] = d; d = td;
                        int ti = bi[k]; bi[k] = idx; idx = ti;
                    }
                }
                kth = best[KNN - 1];
            }
        }
        float d19 = sqrtf(fmaxf(best[KNN - 1], 1e-30f));
        float h = fmaxf(d19, 1e-12f);
        float inv2h2 = 1.f / (2.f * h * h);
        float ws = 0.f, wv[KNN];
#pragma unroll
        for (int o = 0; o < KNN; o++) {
            float d = sqrtf(fmaxf(best[o], 1e-30f));
            wv[o] = expf(-d * d * inv2h2);
            ws += wv[o];
        }
        float inv = 1.f / (ws + 1e-12f);
#pragma unroll
        for (int o = 0; o < KNN; o++) { selW[w][o] = wv[o] * inv; selI[w][o] = bi[o]; }
    }
    __syncwarp();

    int d0 = l * 2;
    float u0 = 0.f, u1 = 0.f;
#pragma unroll
    for (int o = 0; o < KNN; o++) {
        float wt = selW[w][o]; int idx = selI[w][o];
        float2 v = *reinterpret_cast<const float2*>(&velocity[idx * 64 + d0]);
        u0 += wt * v.x; u1 += wt * v.y;
    }
    float x0 = out[qi * 66 + d0], x1 = out[qi * 66 + d0 + 1];
    float pd = u0 * x0 + u1 * x1;
    float pu = u0 * u0 + u1 * u1;
    float px = x0 * x0 + x1 * x1;
#pragma unroll
    for (int o = 16; o; o >>= 1) {
        pd += __shfl_xor_sync(0xffffffffu, pd, o);
        pu += __shfl_xor_sync(0xffffffffu, pu, o);
        px += __shfl_xor_sync(0xffffffffu, px, o);
    }
    if (l == 0) {
        float nu = fmaxf(sqrtf(pu), 1e-8f);
        float nx = fmaxf(sqrtf(px), 1e-8f);
        out[qi * 66 + 64] = 1.f - pd / (nu * nx);
        out[qi * 66 + 65] = pu - 2.f * pd + px;
    }
}

// ---------------------------------------------------------------------------
extern "C" void kernel_launch(void* const* d_in, const int* in_sizes, int n_in,
                              void* d_out, int out_size)
{
    const float* t        = (const float*)d_in[0];
    const float* z        = (const float*)d_in[1];
    const float* data     = (const float*)d_in[2];
    const float* velocity = (const float*)d_in[3];
    const float* W1       = (const float*)d_in[4];
    const float* b1       = (const float*)d_in[5];
    const float* W2       = (const float*)d_in[6];
    const float* b2       = (const float*)d_in[7];
    float* out = (float*)d_out;

    cudaFuncSetAttribute(scr_k, cudaFuncAttributeMaxDynamicSharedMemorySize,
                         SCR_SMEM);

    prep_k<<<NP / 256, 256>>>(data);
    mlp_k<<<BQ / 16, 256>>>(t, z, W1, b1, W2, b2, out);
    scr_k<<<dim3(BQ / QBK, NSPLIT), 256, SCR_SMEM>>>(z);
    fin2_k<<<BQ / 8, 256>>>(z, data, velocity, out);
}

// round 12
// speedup vs baseline: 1.5766x; 1.5766x over previous
#include <cuda_runtime.h>
#include <cuda_bf16.h>
#include <cstdint>
#include <math.h>

#define N_DATA 100000
#define NP     100352              // 1568 * 64
#define TILE   64
#define N_TILES (NP / TILE)        // 1568
#define NSPLIT 16
#define TPS    (N_TILES / NSPLIT)  // 98 tiles per split
#define SPLIT_PTS (TPS * TILE)     // 6272
#define D      64
#define BQ     2048
#define QBK    64                  // queries per screening CTA (M)
#define KNN    20
#define SAMPK  21                  // sample top-k for threshold
#define SAMP_TILES 64              // 4096 sample points
#define CAP    2048                // candidate buffer per query

__device__ float g_bt[NP * D];     // tf32-rounded, k-permuted, point-major rows
__device__ float g_pp[NP];         // exact fp32 ||p||^2 (1e30 pad)
__device__ float g_tau[BQ];        // screening threshold per query
__device__ int   g_cnt[BQ];
__device__ int   g_cbuf[BQ * CAP];

// smem byte offsets (samp_k / scr2_k). Rows: 68-float pitch.
#define OFF_Q    0                 // 64 x 68 floats = 17408
#define OFF_B    17408             // [buf] 17408 : ends 52224
#define OFF_DIST 52224             // 64 x 68 floats
#define OFF_PP   69632             // 2 x 64 floats
#define OFF_QQ   70144             // 64 floats
#define SCR_SMEM 70400
// samp_k epilogue lists alias Q/B region
#define OFF_LD   0                 // 256*SAMPK floats
#define OFF_LI   21504             // 256*SAMPK ints

// ---------------------------------------------------------------------------
__device__ __forceinline__ void cp_async16(unsigned s, const void* gmem) {
    asm volatile("cp.async.cg.shared.global [%0], [%1], 16;" :: "r"(s), "l"(gmem));
}
#define CP_COMMIT() asm volatile("cp.async.commit_group;")
#define CP_WAIT1()  asm volatile("cp.async.wait_group 1;")
#define CP_WAIT0()  asm volatile("cp.async.wait_group 0;")

__device__ __forceinline__ unsigned smem_u32(const void* p) {
    unsigned a;
    asm("{ .reg .u64 t; cvta.to.shared.u64 t, %1; cvt.u32.u64 %0, t; }"
        : "=r"(a) : "l"(p));
    return a;
}
__device__ __forceinline__ unsigned f2u(float x) { return __float_as_uint(x); }

__device__ __forceinline__ void mma_tf32(float* c,
    unsigned a0, unsigned a1, unsigned a2, unsigned a3,
    unsigned b0, unsigned b1)
{
    asm volatile(
        "mma.sync.aligned.m16n8k8.row.col.f32.tf32.tf32.f32 "
        "{%0,%1,%2,%3}, {%4,%5,%6,%7}, {%8,%9}, {%0,%1,%2,%3};"
        : "+f"(c[0]), "+f"(c[1]), "+f"(c[2]), "+f"(c[3])
        : "r"(a0), "r"(a1), "r"(a2), "r"(a3), "r"(b0), "r"(b1));
}

__device__ __forceinline__ void insS(float d, int idx, float* best, int* bestI,
                                     float& kth) {
    if (d < kth) {
#pragma unroll
        for (int k = 0; k < SAMPK; k++) {
            if (d < best[k]) {
                float td = best[k]; best[k] = d; d = td;
                int ti = bestI[k]; bestI[k] = idx; idx = ti;
            }
        }
        kth = best[SAMPK - 1];
    }
}

// ---------------------------------------------------------------------------
// Prep: tf32-round data into k-permuted point-major rows + exact ||p||^2
// (k-perm: mma fragment pairs (k, k+4) adjacent -> single LDS.64)
// ---------------------------------------------------------------------------
__global__ void prep_k(const float* __restrict__ data) {
    int p = blockIdx.x * 256 + threadIdx.x;
    if (p >= NP) return;
    bool v = p < N_DATA;
    float pp = 0.f;
#pragma unroll
    for (int c8 = 0; c8 < 8; c8++) {
        float buf[8];
#pragma unroll
        for (int k = 0; k < 8; k++) {
            float x = v ? data[p * D + c8 * 8 + k] : 0.f;
            pp += x * x;
            unsigned h; asm volatile("cvt.rna.tf32.f32 %0, %1;" : "=r"(h) : "f"(x));
            buf[(k & 3) * 2 + ((k >> 2) & 1)] = __uint_as_float(h);
        }
        *reinterpret_cast<float4*>(&g_bt[p * D + c8 * 8]) =
            make_float4(buf[0], buf[1], buf[2], buf[3]);
        *reinterpret_cast<float4*>(&g_bt[p * D + c8 * 8 + 4]) =
            make_float4(buf[4], buf[5], buf[6], buf[7]);
    }
    g_pp[p] = v ? pp : 1e30f;
}

__global__ void zero_k() {
    int i = blockIdx.x * 256 + threadIdx.x;
    if (i < BQ) g_cnt[i] = 0;
}

// ---------------------------------------------------------------------------
// MLP: x_dot = relu([x,t] @ W1 + b1) @ W2 + b2 ; write into out[:, 0:64]
// ---------------------------------------------------------------------------
__global__ __launch_bounds__(256) void mlp_k(
    const float* __restrict__ t, const float* __restrict__ z,
    const float* __restrict__ W1, const float* __restrict__ b1,
    const float* __restrict__ W2, const float* __restrict__ b2,
    float* __restrict__ out)
{
    __shared__ float sIn[16 * 68];
    __shared__ float sH[16 * 258];
    int tid = threadIdx.x;
    int r0 = blockIdx.x * 16;
    float tv = t[0];
    for (int i = tid; i < 16 * 65; i += 256) {
        int r = i / 65, c = i % 65;
        sIn[r * 68 + c] = (c < 64) ? z[(r0 + r) * 66 + c] : tv;
    }
    __syncthreads();
    {
        int r = tid & 15, jb = tid >> 4;
#pragma unroll
        for (int jj = 0; jj < 16; jj++) {
            int j = jb + jj * 16;
            float acc = b1[j];
#pragma unroll
            for (int i = 0; i < 65; i++) acc += sIn[r * 68 + i] * W1[i * 256 + j];
            sH[r * 258 + j] = fmaxf(acc, 0.f);
        }
    }
    __syncthreads();
    {
        int r = tid >> 4, db = tid & 15;
        int d0 = db * 4;
        float a0 = b2[d0], a1 = b2[d0 + 1], a2 = b2[d0 + 2], a3 = b2[d0 + 3];
#pragma unroll 8
        for (int j = 0; j < 256; j++) {
            float hv = sH[r * 258 + j];
            float4 w = *reinterpret_cast<const float4*>(W2 + j * 64 + d0);
            a0 += hv * w.x; a1 += hv * w.y; a2 += hv * w.z; a3 += hv * w.w;
        }
        int gq = r0 + r;
        out[gq * 66 + d0 + 0] = a0;
        out[gq * 66 + d0 + 1] = a1;
        out[gq * 66 + d0 + 2] = a2;
        out[gq * 66 + d0 + 3] = a3;
    }
}

// ---------------------------------------------------------------------------
// Shared tile machinery for samp_k / scr2_k
// ---------------------------------------------------------------------------
__device__ __forceinline__ void loadB(unsigned smb, int tile, int buf, int tid) {
    const char* src = (const char*)g_bt + (size_t)tile * 16384;
    unsigned dst = smb + OFF_B + buf * 17408;
#pragma unroll
    for (int i = 0; i < 4; i++) {
        int c = tid + i * 256;             // 1024 = 64 rows x 16 chunks
        int r = c >> 4, ch = c & 15;
        cp_async16(dst + r * 272 + ch * 16, src + r * 256 + ch * 16);
    }
    if (tid < 16)
        cp_async16(smb + OFF_PP + buf * 256 + tid * 16,
                   (const char*)g_pp + (size_t)tile * 256 + tid * 16);
}

__device__ __forceinline__ void stage_queries(char* sm, const float* z,
                                              int q0, int tid) {
    float* Qt = reinterpret_cast<float*>(sm + OFF_Q);
#pragma unroll
    for (int i = 0; i < 2; i++) {
        int task = tid + i * 256;          // 512 = 64 rows x 8 chunks
        int r = task >> 3, c8 = task & 7;
#pragma unroll
        for (int k = 0; k < 8; k++) {
            float x = z[(q0 + r) * 66 + c8 * 8 + k];
            unsigned h; asm volatile("cvt.rna.tf32.f32 %0, %1;" : "=r"(h) : "f"(x));
            Qt[r * 68 + c8 * 8 + (k & 3) * 2 + ((k >> 2) & 1)] = __uint_as_float(h);
        }
    }
    if (tid < QBK) {
        float s = 0.f;
#pragma unroll 8
        for (int k = 0; k < D; k++) { float x = z[(q0 + tid) * 66 + k]; s += x * x; }
        *reinterpret_cast<float*>(sm + OFF_QQ + tid * 4) = s;
    }
}

// compute 64x64 tf32 distance tile into Dist (all 8 warps)
__device__ __forceinline__ void mma_tile(char* sm, int cur, int wid, int lane) {
    int mstripe = wid >> 1, nhalf = wid & 1;
    int g = lane >> 2, tm = lane & 3;
    int r0q = mstripe * 16 + g, r1q = r0q + 8;
    const float* Qt = reinterpret_cast<const float*>(sm + OFF_Q);
    const float* Bt = reinterpret_cast<const float*>(sm + OFF_B + cur * 17408);
    float qq0 = *reinterpret_cast<const float*>(sm + OFF_QQ + r0q * 4);
    float qq1 = *reinterpret_cast<const float*>(sm + OFF_QQ + r1q * 4);

    float acc[4][4];
#pragma unroll
    for (int nt = 0; nt < 4; nt++)
#pragma unroll
        for (int i = 0; i < 4; i++) acc[nt][i] = 0.f;

#pragma unroll
    for (int kc = 0; kc < 8; kc++) {
        int ko = kc * 8 + 2 * tm;
        float2 a0 = *reinterpret_cast<const float2*>(&Qt[r0q * 68 + ko]);
        float2 a1 = *reinterpret_cast<const float2*>(&Qt[r1q * 68 + ko]);
#pragma unroll
        for (int nt = 0; nt < 4; nt++) {
            int pr = nhalf * 32 + nt * 8 + g;
            float2 b = *reinterpret_cast<const float2*>(&Bt[pr * 68 + ko]);
            mma_tf32(acc[nt], f2u(a0.x), f2u(a1.x), f2u(a0.y), f2u(a1.y),
                     f2u(b.x), f2u(b.y));
        }
    }
    const float* pp = reinterpret_cast<const float*>(sm + OFF_PP + cur * 256);
    float* Dist = reinterpret_cast<float*>(sm + OFF_DIST);
#pragma unroll
    for (int nt = 0; nt < 4; nt++) {
        int c0 = nhalf * 32 + nt * 8 + 2 * tm;
        float pp0 = pp[c0], pp1 = pp[c0 + 1];
        *reinterpret_cast<float2*>(&Dist[r0q * 68 + c0]) =
            make_float2(qq0 + pp0 - 2.f * acc[nt][0],
                        qq0 + pp1 - 2.f * acc[nt][1]);
        *reinterpret_cast<float2*>(&Dist[r1q * 68 + c0]) =
            make_float2(qq1 + pp0 - 2.f * acc[nt][2],
                        qq1 + pp1 - 2.f * acc[nt][3]);
    }
}

// ---------------------------------------------------------------------------
// samp_k: exact-ish tf32 dists vs points 0..4095; per-query 21st smallest -> tau
// ---------------------------------------------------------------------------
__global__ __launch_bounds__(256, 2) void samp_k(const float* __restrict__ z)
{
    extern __shared__ char sm[];
    unsigned smb = smem_u32(sm);
    int tid = threadIdx.x, lane = tid & 31, wid = tid >> 5;
    int q0 = blockIdx.x * QBK;

    loadB(smb, 0, 0, tid); CP_COMMIT();
    loadB(smb, 1, 1, tid); CP_COMMIT();
    stage_queries(sm, z, q0, tid);
    __syncthreads();

    int sq_q = tid >> 2, sgrp = tid & 3;
    float best[SAMPK]; int bestI[SAMPK]; float kth = 3.4e38f;
#pragma unroll
    for (int k = 0; k < SAMPK; k++) { best[k] = 3.4e38f; bestI[k] = 0; }

    for (int t = 0; t < SAMP_TILES; t++) {
        int cur = t & 1;
        if (t + 1 < SAMP_TILES) CP_WAIT1(); else CP_WAIT0();
        __syncthreads();
        mma_tile(sm, cur, wid, lane);
        __syncthreads();
        if (t + 2 < SAMP_TILES) { loadB(smb, t + 2, cur, tid); CP_COMMIT(); }

        const float* Dist = reinterpret_cast<const float*>(sm + OFF_DIST);
        int pb = t * TILE + sgrp * 16;
#pragma unroll
        for (int c4 = 0; c4 < 4; c4++) {
            float4 v = *reinterpret_cast<const float4*>(
                &Dist[sq_q * 68 + sgrp * 16 + c4 * 4]);
            insS(v.x, pb + c4 * 4 + 0, best, bestI, kth);
            insS(v.y, pb + c4 * 4 + 1, best, bestI, kth);
            insS(v.z, pb + c4 * 4 + 2, best, bestI, kth);
            insS(v.w, pb + c4 * 4 + 3, best, bestI, kth);
        }
        __syncthreads();
    }
    __syncthreads();

    float* listD = reinterpret_cast<float*>(sm + OFF_LD);
#pragma unroll
    for (int k = 0; k < SAMPK; k++) listD[tid * SAMPK + k] = best[k];
    __syncthreads();
    if (tid < QBK) {
        int ptr[4] = {0, 0, 0, 0};
        float bd = 3.5e38f;
        for (int o = 0; o < SAMPK; o++) {
            bd = 3.5e38f; int bl = 0;
#pragma unroll
            for (int l = 0; l < 4; l++) {
                if (ptr[l] < SAMPK) {
                    float v = listD[(tid * 4 + l) * SAMPK + ptr[l]];
                    if (v < bd) { bd = v; bl = l; }
                }
            }
            ptr[bl]++;
        }
        g_tau[q0 + tid] = bd + 1.0f;   // 21st smallest + margin
    }
}

// ---------------------------------------------------------------------------
// scr2_k: threshold screen — no sorted lists, rare atomic append.
// ---------------------------------------------------------------------------
__global__ __launch_bounds__(256, 3) void scr2_k(const float* __restrict__ z)
{
    extern __shared__ char sm[];
    unsigned smb = smem_u32(sm);
    int tid = threadIdx.x, lane = tid & 31, wid = tid >> 5;
    int q0 = blockIdx.x * QBK;
    int split = blockIdx.y;
    int tb = split * TPS;

    loadB(smb, tb + 0, 0, tid); CP_COMMIT();
    loadB(smb, tb + 1, 1, tid); CP_COMMIT();
    stage_queries(sm, z, q0, tid);
    __syncthreads();

    int sq_q = tid >> 2, sgrp = tid & 3;
    int gq = q0 + sq_q;
    float tau = g_tau[gq];

    for (int t = 0; t < TPS; t++) {
        int cur = t & 1;
        if (t + 1 < TPS) CP_WAIT1(); else CP_WAIT0();
        __syncthreads();
        mma_tile(sm, cur, wid, lane);
        __syncthreads();
        if (t + 2 < TPS) { loadB(smb, tb + t + 2, cur, tid); CP_COMMIT(); }

        const float* Dist = reinterpret_cast<const float*>(sm + OFF_DIST);
        int pb = split * SPLIT_PTS + t * TILE + sgrp * 16;
#pragma unroll
        for (int c4 = 0; c4 < 4; c4++) {
            float4 v = *reinterpret_cast<const float4*>(
                &Dist[sq_q * 68 + sgrp * 16 + c4 * 4]);
            bool hit = (v.x <= tau) | (v.y <= tau) | (v.z <= tau) | (v.w <= tau);
            if (__any_sync(0xffffffffu, hit)) {
                int base = pb + c4 * 4;
                if (v.x <= tau) { int p_ = atomicAdd(&g_cnt[gq], 1); if (p_ < CAP) g_cbuf[gq * CAP + p_] = base + 0; }
                if (v.y <= tau) { int p_ = atomicAdd(&g_cnt[gq], 1); if (p_ < CAP) g_cbuf[gq * CAP + p_] = base + 1; }
                if (v.z <= tau) { int p_ = atomicAdd(&g_cnt[gq], 1); if (p_ < CAP) g_cbuf[gq * CAP + p_] = base + 2; }
                if (v.w <= tau) { int p_ = atomicAdd(&g_cnt[gq], 1); if (p_ < CAP) g_cbuf[gq * CAP + p_] = base + 3; }
            }
        }
        __syncthreads();
    }
}

// ---------------------------------------------------------------------------
// fin3_k: one CTA per query — exact refine of candidates, top-20, metrics.
// ---------------------------------------------------------------------------
__global__ __launch_bounds__(256) void fin3_k(
    const float* __restrict__ z, const float* __restrict__ data,
    const float* __restrict__ velocity, float* __restrict__ out)
{
    __shared__ float sQ[64];
    __shared__ float sqq;
    __shared__ float sD[CAP];
    __shared__ int   sI[CAP];
    __shared__ float redV[8];
    __shared__ int   redI[8];
    __shared__ float selD[KNN];
    __shared__ int   selI2[KNN];
    __shared__ float selW[KNN];

    int tid = threadIdx.x, w = tid >> 5, l = tid & 31;
    int q = blockIdx.x;

    if (w == 0) {
        float part = 0.f;
        for (int k = l; k < 64; k += 32) {
            float x = z[q * 66 + k];
            sQ[k] = x; part += x * x;
        }
#pragma unroll
        for (int o = 16; o; o >>= 1) part += __shfl_xor_sync(0xffffffffu, part, o);
        if (l == 0) sqq = part;
    }
    __syncthreads();
    float qq = sqq;

    int n = g_cnt[q]; if (n > CAP) n = CAP;

    for (int c = tid; c < n; c += 256) {
        int idx = g_cbuf[q * CAP + c];
        float dt = 0.f, pp = 0.f;
#pragma unroll
        for (int k4 = 0; k4 < 16; k4++) {
            float4 p = *reinterpret_cast<const float4*>(&data[idx * 64 + k4 * 4]);
            pp += p.x * p.x + p.y * p.y + p.z * p.z + p.w * p.w;
            dt += sQ[k4 * 4 + 0] * p.x + sQ[k4 * 4 + 1] * p.y
                + sQ[k4 * 4 + 2] * p.z + sQ[k4 * 4 + 3] * p.w;
        }
        sD[c] = qq + pp - 2.f * dt;
        sI[c] = idx;
    }
    __syncthreads();

    // 20 rounds of block argmin
    for (int r = 0; r < KNN; r++) {
        float bv = 3.4e38f; int bi = -1;
        for (int c = tid; c < n; c += 256)
            if (sD[c] < bv) { bv = sD[c]; bi = c; }
#pragma unroll
        for (int o = 16; o; o >>= 1) {
            float ov = __shfl_xor_sync(0xffffffffu, bv, o);
            int   oi = __shfl_xor_sync(0xffffffffu, bi, o);
            if (ov < bv) { bv = ov; bi = oi; }
        }
        if (l == 0) { redV[w] = bv; redI[w] = bi; }
        __syncthreads();
        if (tid == 0) {
            float fv = 3.4e38f; int fi = -1;
#pragma unroll
            for (int ww = 0; ww < 8; ww++)
                if (redV[ww] < fv) { fv = redV[ww]; fi = redI[ww]; }
            selD[r] = fv; selI2[r] = sI[fi];
            sD[fi] = 3.4e38f;
        }
        __syncthreads();
    }

    if (tid == 0) {
        float d19 = sqrtf(fmaxf(selD[KNN - 1], 1e-30f));
        float h = fmaxf(d19, 1e-12f);
        float inv2h2 = 1.f / (2.f * h * h);
        float ws = 0.f, wv[KNN];
#pragma unroll
        for (int o = 0; o < KNN; o++) {
            float d = sqrtf(fmaxf(selD[o], 1e-30f));
            wv[o] = expf(-d * d * inv2h2);
            ws += wv[o];
        }
        float inv = 1.f / (ws + 1e-12f);
#pragma unroll
        for (int o = 0; o < KNN; o++) selW[o] = wv[o] * inv;
    }
    __syncthreads();

    if (w == 0) {
        int d0 = l * 2;
        float u0 = 0.f, u1 = 0.f;
#pragma unroll
        for (int o = 0; o < KNN; o++) {
            float wt = selW[o]; int idx = selI2[o];
            float2 v = *reinterpret_cast<const float2*>(&velocity[idx * 64 + d0]);
            u0 += wt * v.x; u1 += wt * v.y;
        }
        float x0 = out[q * 66 + d0], x1 = out[q * 66 + d0 + 1];
        float pd = u0 * x0 + u1 * x1;
        float pu = u0 * u0 + u1 * u1;
        float px = x0 * x0 + x1 * x1;
#pragma unroll
        for (int o = 16; o; o >>= 1) {
            pd += __shfl_xor_sync(0xffffffffu, pd, o);
            pu += __shfl_xor_sync(0xffffffffu, pu, o);
            px += __shfl_xor_sync(0xffffffffu, px, o);
        }
        if (l == 0) {
            float nu = fmaxf(sqrtf(pu), 1e-8f);
            float nx = fmaxf(sqrtf(px), 1e-8f);
            out[q * 66 + 64] = 1.f - pd / (nu * nx);
            out[q * 66 + 65] = pu - 2.f * pd + px;
        }
    }
}

// ---------------------------------------------------------------------------
extern "C" void kernel_launch(void* const* d_in, const int* in_sizes, int n_in,
                              void* d_out, int out_size)
{
    const float* t        = (const float*)d_in[0];
    const float* z        = (const float*)d_in[1];
    const float* data     = (const float*)d_in[2];
    const float* velocity = (const float*)d_in[3];
    const float* W1       = (const float*)d_in[4];
    const float* b1       = (const float*)d_in[5];
    const float* W2       = (const float*)d_in[6];
    const float* b2       = (const float*)d_in[7];
    float* out = (float*)d_out;

    cudaFuncSetAttribute(samp_k, cudaFuncAttributeMaxDynamicSharedMemorySize,
                         SCR_SMEM);
    cudaFuncSetAttribute(scr2_k, cudaFuncAttributeMaxDynamicSharedMemorySize,
                         SCR_SMEM);

    prep_k<<<NP / 256, 256>>>(data);
    zero_k<<<BQ / 256, 256>>>();
    mlp_k<<<BQ / 16, 256>>>(t, z, W1, b1, W2, b2, out);
    samp_k<<<BQ / QBK, 256, SCR_SMEM>>>(z);
    scr2_k<<<dim3(BQ / QBK, NSPLIT), 256, SCR_SMEM>>>(z);
    fin3_k<<<BQ, 256>>>(z, data, velocity, out);
}

// round 13
// speedup vs baseline: 3.0174x; 1.9139x over previous
#include <cuda_runtime.h>
#include <cuda_bf16.h>
#include <cstdint>
#include <math.h>

#define N_DATA 100000
#define NP     100352              // 1568 * 64
#define TILE   64
#define N_TILES (NP / TILE)        // 1568
#define NSPLIT 16
#define TPS    (N_TILES / NSPLIT)  // 98 tiles per split
#define SPLIT_PTS (TPS * TILE)     // 6272
#define D      64
#define BQ     2048
#define QBK    64                  // queries per CTA (M)
#define KNN    20
#define SAMPK  21
#define SAMP_SPLITS 4
#define SAMP_TPS 16                // 16 tiles per samp CTA (4096 sample pts total)
#define CAP    2048

#define SCALE_Q 23.090909f         // 127 / 5.5
#define INV_S2  (1.0f / (SCALE_Q * SCALE_Q))

__device__ float g_bt[4096 * D];   // tf32-rounded k-permuted rows (sample pts)
__device__ signed char g_b8[NP * D];  // int8 quantized rows (64B each)
__device__ float g_pp[NP];         // exact fp32 ||p||^2 (1e30 pad)
__device__ float g_sampD[BQ * SAMP_SPLITS * SAMPK];
__device__ float g_tau[BQ];
__device__ int   g_cnt[BQ];
__device__ int   g_cbuf[BQ * CAP];

// ---- samp_k smem layout (tf32, 68-float pitch) ----
#define OFF_Q    0                 // 64 x 68 floats = 17408
#define OFF_B    17408             // [buf] 17408 : ends 52224
#define OFF_DIST 52224
#define OFF_PP   69632
#define OFF_QQ   70144
#define SCR_SMEM 70400
#define OFF_LD   0                 // epilogue alias
// ---- scr2_k smem layout (int8, 80B pitch rows) ----
#define S2_Q     0                 // 64 x 80 = 5120
#define S2_B     5120              // [buf] 5120 : ends 15360
#define S2_PP    15360             // 2 x 64 floats
#define S2_QQ    15872             // 64 floats
#define S2_SMEM  16128

// ---------------------------------------------------------------------------
__device__ __forceinline__ void cp_async16(unsigned s, const void* gmem) {
    asm volatile("cp.async.cg.shared.global [%0], [%1], 16;" :: "r"(s), "l"(gmem));
}
#define CP_COMMIT() asm volatile("cp.async.commit_group;")
#define CP_WAIT1()  asm volatile("cp.async.wait_group 1;")
#define CP_WAIT0()  asm volatile("cp.async.wait_group 0;")

__device__ __forceinline__ unsigned smem_u32(const void* p) {
    unsigned a;
    asm("{ .reg .u64 t; cvta.to.shared.u64 t, %1; cvt.u32.u64 %0, t; }"
        : "=r"(a) : "l"(p));
    return a;
}
__device__ __forceinline__ unsigned f2u(float x) { return __float_as_uint(x); }

__device__ __forceinline__ void mma_tf32(float* c,
    unsigned a0, unsigned a1, unsigned a2, unsigned a3,
    unsigned b0, unsigned b1)
{
    asm volatile(
        "mma.sync.aligned.m16n8k8.row.col.f32.tf32.tf32.f32 "
        "{%0,%1,%2,%3}, {%4,%5,%6,%7}, {%8,%9}, {%0,%1,%2,%3};"
        : "+f"(c[0]), "+f"(c[1]), "+f"(c[2]), "+f"(c[3])
        : "r"(a0), "r"(a1), "r"(a2), "r"(a3), "r"(b0), "r"(b1));
}

__device__ __forceinline__ void mma_s8(int* c, const unsigned* a,
                                       unsigned b0, unsigned b1)
{
    asm volatile(
        "mma.sync.aligned.m16n8k32.row.col.s32.s8.s8.s32 "
        "{%0,%1,%2,%3}, {%4,%5,%6,%7}, {%8,%9}, {%0,%1,%2,%3};"
        : "+r"(c[0]), "+r"(c[1]), "+r"(c[2]), "+r"(c[3])
        : "r"(a[0]), "r"(a[1]), "r"(a[2]), "r"(a[3]), "r"(b0), "r"(b1));
}

__device__ __forceinline__ void insS(float d, float* best, float& kth) {
    if (d < kth) {
#pragma unroll
        for (int k = 0; k < SAMPK; k++) {
            if (d < best[k]) { float td = best[k]; best[k] = d; d = td; }
        }
        kth = best[SAMPK - 1];
    }
}

__device__ __forceinline__ int quant8(float x) {
    float c = fminf(fmaxf(x, -5.5f), 5.5f);
    return __float2int_rn(c * SCALE_Q);
}

// ---------------------------------------------------------------------------
// Prep: int8 rows for all points; tf32 k-permuted rows for sample pts; ||p||^2
// ---------------------------------------------------------------------------
__global__ void prep_k(const float* __restrict__ data) {
    int p = blockIdx.x * 256 + threadIdx.x;
    if (p >= NP) return;
    bool v = p < N_DATA;
    float pp = 0.f;
    unsigned pk[16];
#pragma unroll
    for (int c4 = 0; c4 < 16; c4++) {
        unsigned w = 0;
#pragma unroll
        for (int j = 0; j < 4; j++) {
            float x = v ? data[p * D + c4 * 4 + j] : 0.f;
            pp += x * x;
            w |= ((unsigned)(quant8(x) & 0xFF)) << (j * 8);
        }
        pk[c4] = w;
    }
#pragma unroll
    for (int i = 0; i < 4; i++)
        *reinterpret_cast<uint4*>(&g_b8[p * 64 + i * 16]) =
            make_uint4(pk[i * 4], pk[i * 4 + 1], pk[i * 4 + 2], pk[i * 4 + 3]);
    g_pp[p] = v ? pp : 1e30f;

    if (p < 4096) {
#pragma unroll
        for (int c8 = 0; c8 < 8; c8++) {
            float buf[8];
#pragma unroll
            for (int k = 0; k < 8; k++) {
                float x = data[p * D + c8 * 8 + k];   // p<4096 < N_DATA
                unsigned h; asm volatile("cvt.rna.tf32.f32 %0, %1;" : "=r"(h) : "f"(x));
                buf[(k & 3) * 2 + ((k >> 2) & 1)] = __uint_as_float(h);
            }
            *reinterpret_cast<float4*>(&g_bt[p * D + c8 * 8]) =
                make_float4(buf[0], buf[1], buf[2], buf[3]);
            *reinterpret_cast<float4*>(&g_bt[p * D + c8 * 8 + 4]) =
                make_float4(buf[4], buf[5], buf[6], buf[7]);
        }
    }
}

__global__ void zero_k() {
    int i = blockIdx.x * 256 + threadIdx.x;
    if (i < BQ) g_cnt[i] = 0;
}

// ---------------------------------------------------------------------------
// MLP
// ---------------------------------------------------------------------------
__global__ __launch_bounds__(256) void mlp_k(
    const float* __restrict__ t, const float* __restrict__ z,
    const float* __restrict__ W1, const float* __restrict__ b1,
    const float* __restrict__ W2, const float* __restrict__ b2,
    float* __restrict__ out)
{
    __shared__ float sIn[16 * 68];
    __shared__ float sH[16 * 258];
    int tid = threadIdx.x;
    int r0 = blockIdx.x * 16;
    float tv = t[0];
    for (int i = tid; i < 16 * 65; i += 256) {
        int r = i / 65, c = i % 65;
        sIn[r * 68 + c] = (c < 64) ? z[(r0 + r) * 66 + c] : tv;
    }
    __syncthreads();
    {
        int r = tid & 15, jb = tid >> 4;
#pragma unroll
        for (int jj = 0; jj < 16; jj++) {
            int j = jb + jj * 16;
            float acc = b1[j];
#pragma unroll
            for (int i = 0; i < 65; i++) acc += sIn[r * 68 + i] * W1[i * 256 + j];
            sH[r * 258 + j] = fmaxf(acc, 0.f);
        }
    }
    __syncthreads();
    {
        int r = tid >> 4, db = tid & 15;
        int d0 = db * 4;
        float a0 = b2[d0], a1 = b2[d0 + 1], a2 = b2[d0 + 2], a3 = b2[d0 + 3];
#pragma unroll 8
        for (int j = 0; j < 256; j++) {
            float hv = sH[r * 258 + j];
            float4 w = *reinterpret_cast<const float4*>(W2 + j * 64 + d0);
            a0 += hv * w.x; a1 += hv * w.y; a2 += hv * w.z; a3 += hv * w.w;
        }
        int gq = r0 + r;
        out[gq * 66 + d0 + 0] = a0;
        out[gq * 66 + d0 + 1] = a1;
        out[gq * 66 + d0 + 2] = a2;
        out[gq * 66 + d0 + 3] = a3;
    }
}

// ---------------------------------------------------------------------------
// samp_k machinery (tf32)
// ---------------------------------------------------------------------------
__device__ __forceinline__ void loadBt(unsigned smb, int tile, int buf, int tid) {
    const char* src = (const char*)g_bt + (size_t)tile * 16384;
    unsigned dst = smb + OFF_B + buf * 17408;
#pragma unroll
    for (int i = 0; i < 4; i++) {
        int c = tid + i * 256;
        int r = c >> 4, ch = c & 15;
        cp_async16(dst + r * 272 + ch * 16, src + r * 256 + ch * 16);
    }
    if (tid < 16)
        cp_async16(smb + OFF_PP + buf * 256 + tid * 16,
                   (const char*)g_pp + (size_t)tile * 256 + tid * 16);
}

__device__ __forceinline__ void stage_q_tf32(char* sm, const float* z,
                                             int q0, int tid) {
    float* Qt = reinterpret_cast<float*>(sm + OFF_Q);
#pragma unroll
    for (int i = 0; i < 2; i++) {
        int task = tid + i * 256;
        int r = task >> 3, c8 = task & 7;
#pragma unroll
        for (int k = 0; k < 8; k++) {
            float x = z[(q0 + r) * 66 + c8 * 8 + k];
            unsigned h; asm volatile("cvt.rna.tf32.f32 %0, %1;" : "=r"(h) : "f"(x));
            Qt[r * 68 + c8 * 8 + (k & 3) * 2 + ((k >> 2) & 1)] = __uint_as_float(h);
        }
    }
    if (tid < QBK) {
        float s = 0.f;
#pragma unroll 8
        for (int k = 0; k < D; k++) { float x = z[(q0 + tid) * 66 + k]; s += x * x; }
        *reinterpret_cast<float*>(sm + OFF_QQ + tid * 4) = s;
    }
}

__device__ __forceinline__ void mma_tile_tf32(char* sm, int cur, int wid, int lane) {
    int mstripe = wid >> 1, nhalf = wid & 1;
    int g = lane >> 2, tm = lane & 3;
    int r0q = mstripe * 16 + g, r1q = r0q + 8;
    const float* Qt = reinterpret_cast<const float*>(sm + OFF_Q);
    const float* Bt = reinterpret_cast<const float*>(sm + OFF_B + cur * 17408);
    float qq0 = *reinterpret_cast<const float*>(sm + OFF_QQ + r0q * 4);
    float qq1 = *reinterpret_cast<const float*>(sm + OFF_QQ + r1q * 4);

    float acc[4][4];
#pragma unroll
    for (int nt = 0; nt < 4; nt++)
#pragma unroll
        for (int i = 0; i < 4; i++) acc[nt][i] = 0.f;

#pragma unroll
    for (int kc = 0; kc < 8; kc++) {
        int ko = kc * 8 + 2 * tm;
        float2 a0 = *reinterpret_cast<const float2*>(&Qt[r0q * 68 + ko]);
        float2 a1 = *reinterpret_cast<const float2*>(&Qt[r1q * 68 + ko]);
#pragma unroll
        for (int nt = 0; nt < 4; nt++) {
            int pr = nhalf * 32 + nt * 8 + g;
            float2 b = *reinterpret_cast<const float2*>(&Bt[pr * 68 + ko]);
            mma_tf32(acc[nt], f2u(a0.x), f2u(a1.x), f2u(a0.y), f2u(a1.y),
                     f2u(b.x), f2u(b.y));
        }
    }
    const float* pp = reinterpret_cast<const float*>(sm + OFF_PP + cur * 256);
    float* Dist = reinterpret_cast<float*>(sm + OFF_DIST);
#pragma unroll
    for (int nt = 0; nt < 4; nt++) {
        int c0 = nhalf * 32 + nt * 8 + 2 * tm;
        float pp0 = pp[c0], pp1 = pp[c0 + 1];
        *reinterpret_cast<float2*>(&Dist[r0q * 68 + c0]) =
            make_float2(qq0 + pp0 - 2.f * acc[nt][0],
                        qq0 + pp1 - 2.f * acc[nt][1]);
        *reinterpret_cast<float2*>(&Dist[r1q * 68 + c0]) =
            make_float2(qq1 + pp0 - 2.f * acc[nt][2],
                        qq1 + pp1 - 2.f * acc[nt][3]);
    }
}

// ---------------------------------------------------------------------------
// samp_k: tf32 dists vs sample points; per (query, split) sorted top-21 dists
// ---------------------------------------------------------------------------
__global__ __launch_bounds__(256, 2) void samp_k(const float* __restrict__ z)
{
    extern __shared__ char sm[];
    unsigned smb = smem_u32(sm);
    int tid = threadIdx.x, lane = tid & 31, wid = tid >> 5;
    int q0 = blockIdx.x * QBK;
    int split = blockIdx.y;
    int tb = split * SAMP_TPS;

    loadBt(smb, tb + 0, 0, tid); CP_COMMIT();
    loadBt(smb, tb + 1, 1, tid); CP_COMMIT();
    stage_q_tf32(sm, z, q0, tid);
    __syncthreads();

    int sq_q = tid >> 2, sgrp = tid & 3;
    float best[SAMPK]; float kth = 3.4e38f;
#pragma unroll
    for (int k = 0; k < SAMPK; k++) best[k] = 3.4e38f;

    for (int t = 0; t < SAMP_TPS; t++) {
        int cur = t & 1;
        if (t + 1 < SAMP_TPS) CP_WAIT1(); else CP_WAIT0();
        __syncthreads();
        mma_tile_tf32(sm, cur, wid, lane);
        __syncthreads();
        if (t + 2 < SAMP_TPS) { loadBt(smb, tb + t + 2, cur, tid); CP_COMMIT(); }

        const float* Dist = reinterpret_cast<const float*>(sm + OFF_DIST);
#pragma unroll
        for (int c4 = 0; c4 < 4; c4++) {
            float4 v = *reinterpret_cast<const float4*>(
                &Dist[sq_q * 68 + sgrp * 16 + c4 * 4]);
            insS(v.x, best, kth); insS(v.y, best, kth);
            insS(v.z, best, kth); insS(v.w, best, kth);
        }
        __syncthreads();
    }
    __syncthreads();

    float* listD = reinterpret_cast<float*>(sm + OFF_LD);
#pragma unroll
    for (int k = 0; k < SAMPK; k++) listD[tid * SAMPK + k] = best[k];
    __syncthreads();
    if (tid < QBK) {
        int ptr[4] = {0, 0, 0, 0};
        int gbase = ((q0 + tid) * SAMP_SPLITS + split) * SAMPK;
        for (int o = 0; o < SAMPK; o++) {
            float bd = 3.5e38f; int bl = 0;
#pragma unroll
            for (int l = 0; l < 4; l++) {
                if (ptr[l] < SAMPK) {
                    float v = listD[(tid * 4 + l) * SAMPK + ptr[l]];
                    if (v < bd) { bd = v; bl = l; }
                }
            }
            g_sampD[gbase + o] = bd;
            ptr[bl]++;
        }
    }
}

// tau_k: merge 4 sorted 21-lists -> global 21st smallest + margin
__global__ void tau_k() {
    int q = blockIdx.x * 256 + threadIdx.x;
    if (q >= BQ) return;
    const float* L = g_sampD + q * SAMP_SPLITS * SAMPK;
    int ptr[4] = {0, 0, 0, 0};
    float v = 3.5e38f;
    for (int o = 0; o < SAMPK; o++) {
        v = 3.5e38f; int bl = 0;
#pragma unroll
        for (int l = 0; l < 4; l++) {
            if (ptr[l] < SAMPK) {
                float x = L[l * SAMPK + ptr[l]];
                if (x < v) { v = x; bl = l; }
            }
        }
        ptr[bl]++;
    }
    g_tau[q] = v + 2.0f;   // tf32-sample + int8-screen margin
}

// ---------------------------------------------------------------------------
// scr2_k: int8 IMMA threshold screen, register-direct compare + atomic append
// ---------------------------------------------------------------------------
__device__ __forceinline__ void loadB8(unsigned smb, int tile, int buf, int tid) {
    const char* src = (const char*)g_b8 + (size_t)tile * 4096;
    unsigned dst = smb + S2_B + buf * 5120;
    {
        int r = tid >> 2, ch = tid & 3;
        cp_async16(dst + r * 80 + ch * 16, src + tid * 16);
    }
    if (tid < 16)
        cp_async16(smb + S2_PP + buf * 256 + tid * 16,
                   (const char*)g_pp + (size_t)tile * 256 + tid * 16);
}

__global__ __launch_bounds__(256, 3) void scr2_k(const float* __restrict__ z)
{
    extern __shared__ char sm[];
    unsigned smb = smem_u32(sm);
    int tid = threadIdx.x, lane = tid & 31, wid = tid >> 5;
    int q0 = blockIdx.x * QBK;
    int split = blockIdx.y;
    int tb = split * TPS;

    loadB8(smb, tb + 0, 0, tid); CP_COMMIT();
    loadB8(smb, tb + 1, 1, tid); CP_COMMIT();

    // stage queries int8 (80B pitch) + exact qq
#pragma unroll
    for (int i = 0; i < 4; i++) {
        int idx = tid + i * 256;           // 1024 ints = 64 rows x 16
        int r = idx >> 4, c4 = idx & 15;
        unsigned w = 0;
#pragma unroll
        for (int j = 0; j < 4; j++) {
            float x = z[(q0 + r) * 66 + c4 * 4 + j];
            w |= ((unsigned)(quant8(x) & 0xFF)) << (j * 8);
        }
        *reinterpret_cast<unsigned*>(sm + S2_Q + r * 80 + c4 * 4) = w;
    }
    if (tid < QBK) {
        float s = 0.f;
#pragma unroll 8
        for (int k = 0; k < D; k++) { float x = z[(q0 + tid) * 66 + k]; s += x * x; }
        *reinterpret_cast<float*>(sm + S2_QQ + tid * 4) = s;
    }
    __syncthreads();

    int mstripe = wid >> 1, nhalf = wid & 1;
    int g = lane >> 2, tm = lane & 3;
    int r0q = mstripe * 16 + g, r1q = r0q + 8;
    float qq0 = *reinterpret_cast<const float*>(sm + S2_QQ + r0q * 4);
    float qq1 = *reinterpret_cast<const float*>(sm + S2_QQ + r1q * 4);
    int gq0 = q0 + r0q, gq1 = q0 + r1q;
    float tau0 = g_tau[gq0], tau1 = g_tau[gq1];
    const float m2 = -2.f * INV_S2;

    // hoist A fragments (2 kc x 4 regs)
    unsigned a[2][4];
    {
        unsigned base = smb + S2_Q + r0q * 80 + tm * 4;
#pragma unroll
        for (int kc = 0; kc < 2; kc++) {
            a[kc][0] = *reinterpret_cast<unsigned*>((char*)sm + (base - smb) + kc * 32);
            a[kc][1] = *reinterpret_cast<unsigned*>((char*)sm + (base - smb) + 8 * 80 + kc * 32);
            a[kc][2] = *reinterpret_cast<unsigned*>((char*)sm + (base - smb) + kc * 32 + 16);
            a[kc][3] = *reinterpret_cast<unsigned*>((char*)sm + (base - smb) + 8 * 80 + kc * 32 + 16);
        }
    }

    for (int t = 0; t < TPS; t++) {
        int cur = t & 1;
        if (t + 1 < TPS) CP_WAIT1(); else CP_WAIT0();
        __syncthreads();                   // B(t) ready

        int acc[4][4];
#pragma unroll
        for (int nt = 0; nt < 4; nt++)
#pragma unroll
            for (int i = 0; i < 4; i++) acc[nt][i] = 0;

        const char* Bb = sm + S2_B + cur * 5120;
#pragma unroll
        for (int kc = 0; kc < 2; kc++) {
#pragma unroll
            for (int nt = 0; nt < 4; nt++) {
                int pr = nhalf * 32 + nt * 8 + g;
                unsigned b0 = *reinterpret_cast<const unsigned*>(
                    Bb + pr * 80 + tm * 4 + kc * 32);
                unsigned b1 = *reinterpret_cast<const unsigned*>(
                    Bb + pr * 80 + tm * 4 + kc * 32 + 16);
                mma_s8(acc[nt], a[kc], b0, b1);
            }
        }
        __syncthreads();                   // B(cur) consumed
        if (t + 2 < TPS) { loadB8(smb, tb + t + 2, cur, tid); CP_COMMIT(); }

        const float* pp = reinterpret_cast<const float*>(sm + S2_PP + cur * 256);
        int pb = split * SPLIT_PTS + t * TILE;
#pragma unroll
        for (int nt = 0; nt < 4; nt++) {
            int c0 = nhalf * 32 + nt * 8 + tm * 2;
            float pp0 = pp[c0], pp1 = pp[c0 + 1];
            float d00 = fmaf(m2, (float)acc[nt][0], qq0 + pp0);
            float d01 = fmaf(m2, (float)acc[nt][1], qq0 + pp1);
            float d10 = fmaf(m2, (float)acc[nt][2], qq1 + pp0);
            float d11 = fmaf(m2, (float)acc[nt][3], qq1 + pp1);
            if (d00 <= tau0) { int p_ = atomicAdd(&g_cnt[gq0], 1); if (p_ < CAP) g_cbuf[gq0 * CAP + p_] = pb + c0; }
            if (d01 <= tau0) { int p_ = atomicAdd(&g_cnt[gq0], 1); if (p_ < CAP) g_cbuf[gq0 * CAP + p_] = pb + c0 + 1; }
            if (d10 <= tau1) { int p_ = atomicAdd(&g_cnt[gq1], 1); if (p_ < CAP) g_cbuf[gq1 * CAP + p_] = pb + c0; }
            if (d11 <= tau1) { int p_ = atomicAdd(&g_cnt[gq1], 1); if (p_ < CAP) g_cbuf[gq1 * CAP + p_] = pb + c0 + 1; }
        }
    }
}

// ---------------------------------------------------------------------------
// fin3_k: one CTA per query — exact refine, top-20, weights, metrics.
// ---------------------------------------------------------------------------
__global__ __launch_bounds__(256) void fin3_k(
    const float* __restrict__ z, const float* __restrict__ data,
    const float* __restrict__ velocity, float* __restrict__ out)
{
    __shared__ float sQ[64];
    __shared__ float sqq;
    __shared__ float sD[CAP];
    __shared__ int   sI[CAP];
    __shared__ float redV[8];
    __shared__ int   redI[8];
    __shared__ float selD[KNN];
    __shared__ int   selI2[KNN];
    __shared__ float selW[KNN];

    int tid = threadIdx.x, w = tid >> 5, l = tid & 31;
    int q = blockIdx.x;

    if (w == 0) {
        float part = 0.f;
        for (int k = l; k < 64; k += 32) {
            float x = z[q * 66 + k];
            sQ[k] = x; part += x * x;
        }
#pragma unroll
        for (int o = 16; o; o >>= 1) part += __shfl_xor_sync(0xffffffffu, part, o);
        if (l == 0) sqq = part;
    }
    __syncthreads();
    float qq = sqq;

    int n = g_cnt[q]; if (n > CAP) n = CAP;

    for (int c = tid; c < n; c += 256) {
        int idx = g_cbuf[q * CAP + c];
        float dt = 0.f, pp = 0.f;
#pragma unroll
        for (int k4 = 0; k4 < 16; k4++) {
            float4 p = *reinterpret_cast<const float4*>(&data[idx * 64 + k4 * 4]);
            pp += p.x * p.x + p.y * p.y + p.z * p.z + p.w * p.w;
            dt += sQ[k4 * 4 + 0] * p.x + sQ[k4 * 4 + 1] * p.y
                + sQ[k4 * 4 + 2] * p.z + sQ[k4 * 4 + 3] * p.w;
        }
        sD[c] = qq + pp - 2.f * dt;
        sI[c] = idx;
    }
    __syncthreads();

    for (int r = 0; r < KNN; r++) {
        float bv = 3.4e38f; int bi = -1;
        for (int c = tid; c < n; c += 256)
            if (sD[c] < bv) { bv = sD[c]; bi = c; }
#pragma unroll
        for (int o = 16; o; o >>= 1) {
            float ov = __shfl_xor_sync(0xffffffffu, bv, o);
            int   oi = __shfl_xor_sync(0xffffffffu, bi, o);
            if (ov < bv) { bv = ov; bi = oi; }
        }
        if (l == 0) { redV[w] = bv; redI[w] = bi; }
        __syncthreads();
        if (tid == 0) {
            float fv = 3.4e38f; int fi = -1;
#pragma unroll
            for (int ww = 0; ww < 8; ww++)
                if (redV[ww] < fv) { fv = redV[ww]; fi = redI[ww]; }
            selD[r] = fv; selI2[r] = sI[fi];
            sD[fi] = 3.4e38f;
        }
        __syncthreads();
    }

    if (tid == 0) {
        float d19 = sqrtf(fmaxf(selD[KNN - 1], 1e-30f));
        float h = fmaxf(d19, 1e-12f);
        float inv2h2 = 1.f / (2.f * h * h);
        float ws = 0.f, wv[KNN];
#pragma unroll
        for (int o = 0; o < KNN; o++) {
            float d = sqrtf(fmaxf(selD[o], 1e-30f));
            wv[o] = expf(-d * d * inv2h2);
            ws += wv[o];
        }
        float inv = 1.f / (ws + 1e-12f);
#pragma unroll
        for (int o = 0; o < KNN; o++) selW[o] = wv[o] * inv;
    }
    __syncthreads();

    if (w == 0) {
        int d0 = l * 2;
        float u0 = 0.f, u1 = 0.f;
#pragma unroll
        for (int o = 0; o < KNN; o++) {
            float wt = selW[o]; int idx = selI2[o];
            float2 v = *reinterpret_cast<const float2*>(&velocity[idx * 64 + d0]);
            u0 += wt * v.x; u1 += wt * v.y;
        }
        float x0 = out[q * 66 + d0], x1 = out[q * 66 + d0 + 1];
        float pd = u0 * x0 + u1 * x1;
        float pu = u0 * u0 + u1 * u1;
        float px = x0 * x0 + x1 * x1;
#pragma unroll
        for (int o = 16; o; o >>= 1) {
            pd += __shfl_xor_sync(0xffffffffu, pd, o);
            pu += __shfl_xor_sync(0xffffffffu, pu, o);
            px += __shfl_xor_sync(0xffffffffu, px, o);
        }
        if (l == 0) {
            float nu = fmaxf(sqrtf(pu), 1e-8f);
            float nx = fmaxf(sqrtf(px), 1e-8f);
            out[q * 66 + 64] = 1.f - pd / (nu * nx);
            out[q * 66 + 65] = pu - 2.f * pd + px;
        }
    }
}

// ---------------------------------------------------------------------------
extern "C" void kernel_launch(void* const* d_in, const int* in_sizes, int n_in,
                              void* d_out, int out_size)
{
    const float* t        = (const float*)d_in[0];
    const float* z        = (const float*)d_in[1];
    const float* data     = (const float*)d_in[2];
    const float* velocity = (const float*)d_in[3];
    const float* W1       = (const float*)d_in[4];
    const float* b1       = (const float*)d_in[5];
    const float* W2       = (const float*)d_in[6];
    const float* b2       = (const float*)d_in[7];
    float* out = (float*)d_out;

    cudaFuncSetAttribute(samp_k, cudaFuncAttributeMaxDynamicSharedMemorySize,
                         SCR_SMEM);
    cudaFuncSetAttribute(scr2_k, cudaFuncAttributeMaxDynamicSharedMemorySize,
                         S2_SMEM);

    prep_k<<<NP / 256, 256>>>(data);
    zero_k<<<BQ / 256, 256>>>();
    mlp_k<<<BQ / 16, 256>>>(t, z, W1, b1, W2, b2, out);
    samp_k<<<dim3(BQ / QBK, SAMP_SPLITS), 256, SCR_SMEM>>>(z);
    tau_k<<<BQ / 256, 256>>>();
    scr2_k<<<dim3(BQ / QBK, NSPLIT), 256, S2_SMEM>>>(z);
    fin3_k<<<BQ, 256>>>(z, data, velocity, out);
}